// round 12
// baseline (speedup 1.0000x reference)
#include <cuda_runtime.h>
#include <cuda_bf16.h>
#include <cstdint>

#define N_NODES 100000
#define N_EDGES 800000
#define DIM 128
#define NTILES ((N_NODES + 127) / 128)

// ---------------------------------------------------------------------------
// Scratch (allocation-free rule: __device__ globals)
// ---------------------------------------------------------------------------
__device__ float g_v[N_NODES * DIM];
__device__ float g_h[N_NODES * DIM];
__device__ unsigned short g_Wmma[4][2 * 128 * 128];  // prepacked W images

// swizzled byte offset of (row, 16B-chunk kc) in a 256B-row tile
#define SW_OFF(row, kc) ((uint32_t)(row) * 256u + ((uint32_t)(((kc) ^ ((row) & 7))) << 4))

__device__ __forceinline__ uint32_t smem_u32(const void* p) {
    uint32_t a;
    asm("{ .reg .u64 t; cvta.to.shared.u64 t, %1; cvt.u32.u64 %0, t; }"
        : "=r"(a) : "l"(p));
    return a;
}
__device__ __forceinline__ void ldsm_x4(uint32_t& r0, uint32_t& r1, uint32_t& r2,
                                        uint32_t& r3, uint32_t addr) {
    asm volatile("ldmatrix.sync.aligned.m8n8.x4.shared.b16 {%0,%1,%2,%3}, [%4];"
                 : "=r"(r0), "=r"(r1), "=r"(r2), "=r"(r3) : "r"(addr));
}
__device__ __forceinline__ void mma_bf16(float* d, const uint32_t* a, const uint32_t* b) {
    asm volatile(
        "mma.sync.aligned.m16n8k16.row.col.f32.bf16.bf16.f32 "
        "{%0,%1,%2,%3}, {%4,%5,%6,%7}, {%8,%9}, {%0,%1,%2,%3};"
        : "+f"(d[0]), "+f"(d[1]), "+f"(d[2]), "+f"(d[3])
        : "r"(a[0]), "r"(a[1]), "r"(a[2]), "r"(a[3]), "r"(b[0]), "r"(b[1]));
}

// ---------------------------------------------------------------------------
// Prepack W -> g_Wmma: bf16 hi/lo, [n][k] rows (256B), XOR-swizzled 16B chunks
// ---------------------------------------------------------------------------
__global__ __launch_bounds__(256) void prepack_kernel(
    const float* __restrict__ W_v, const float* __restrict__ W_a)
{
    const int idx = blockIdx.x * 256 + threadIdx.x;
    if (idx >= 4 * 2 * 128 * 128) return;
    const int tile = idx >> 15;
    const int seg  = (idx >> 14) & 1;
    const int rem  = idx & 16383;
    const int n    = rem >> 7;
    const int k    = rem & 127;
    const int mat  = tile >> 1;
    const int typ  = tile & 1;

    const float* Wp = (mat ? W_a : W_v) + typ * DIM * DIM;
    const float w = Wp[k * DIM + n];
    __nv_bfloat16 hi = __float2bfloat16_rn(w);
    unsigned short out;
    if (seg == 0) {
        out = *(unsigned short*)&hi;
    } else {
        __nv_bfloat16 lo = __float2bfloat16_rn(w - __bfloat162float(hi));
        out = *(unsigned short*)&lo;
    }
    const uint32_t boff = SW_OFF(n, k >> 3) + (k & 7) * 2;
    g_Wmma[tile][seg * 16384 + (boff >> 1)] = out;
}

// ---------------------------------------------------------------------------
// Persistent typed tensor-core GEMM: Y = X @ W[ntype]
// 256 threads (8 warps, 4m x 2n grid of 32x64 warp tiles). W (both types,
// hi/lo = 128KB) resident in SMEM; register prefetch of next tile's X.
// Inner loop processes B in 32-col halves, reusing 16 B-fragment registers —
// drops peak live regs so ptxas can software-pipeline ldsm across the k-loop.
// do_zero: gemm1 zeroes g_h with fire-and-forget stores behind compute.
// ---------------------------------------------------------------------------
__global__ __launch_bounds__(256) void gemm_mma_kernel(
    const float* __restrict__ X, int mat, int do_zero,
    const int* __restrict__ ntype, float* __restrict__ Y, int N)
{
    extern __shared__ char dsm[];
    const uint32_t sbase = smem_u32(dsm);
    const uint32_t XH = 0, XL = 32768, WB = 65536;   // W: +type*65536 +seg*32768

    const int tid  = threadIdx.x;
    const int wid  = tid >> 5;
    const int lane = tid & 31;

    // ---- fire-and-forget zero of g_h (gemm1 only) -------------------------
    if (do_zero) {
        float4* hp = (float4*)g_h;
        const int total  = N_NODES * DIM / 4;
        const int stride = gridDim.x * 256;
        for (int i = blockIdx.x * 256 + tid; i < total; i += stride)
            hp[i] = make_float4(0.f, 0.f, 0.f, 0.f);
    }

    // ---- load W (both types, hi+lo = 128KB) once -------------------------
    {
        const uint4* srcW0 = (const uint4*)g_Wmma[mat * 2 + 0];
        const uint4* srcW1 = (const uint4*)g_Wmma[mat * 2 + 1];
        uint4* dstW0 = (uint4*)(dsm + WB);
        uint4* dstW1 = (uint4*)(dsm + WB + 65536);
        #pragma unroll
        for (int i = 0; i < 16; i++) {
            dstW0[tid + 256 * i] = srcW0[tid + 256 * i];
            dstW1[tid + 256 * i] = srcW1[tid + 256 * i];
        }
    }

    const int m0 = (wid >> 1) * 32;
    const int n0 = (wid & 1) * 64;
    const int lrow  = tid >> 1;
    const int lkoff = (tid & 1) * 64;

    float4 pf[16];
    int tile = blockIdx.x;
    {
        const int grow = tile * 128 + lrow;
        if (tile < NTILES && grow < N) {
            const float4* xp = (const float4*)(X + (size_t)grow * DIM + lkoff);
            #pragma unroll
            for (int q = 0; q < 16; q++) pf[q] = xp[q];
        } else {
            #pragma unroll
            for (int q = 0; q < 16; q++) pf[q] = make_float4(0, 0, 0, 0);
        }
    }

    while (tile < NTILES) {
        const int row0 = tile * 128;
        const int lastRow = (row0 + 127 < N) ? (row0 + 127) : (N - 1);
        const int t0 = ntype[row0];
        const int t1 = ntype[lastRow];
        const bool mixed = (t0 != t1);
        const int ntile = tile + gridDim.x;

        __syncthreads();   // previous tile's compute done before X overwrite

        // ---- convert prefetched X -> bf16 hi/lo swizzled SMEM -------------
        {
            const int kh = (tid & 1) * 8;
            #pragma unroll
            for (int q = 0; q < 8; q++) {
                float4 f0 = pf[2 * q], f1 = pf[2 * q + 1];
                __nv_bfloat162 h0 = __floats2bfloat162_rn(f0.x, f0.y);
                __nv_bfloat162 h1 = __floats2bfloat162_rn(f0.z, f0.w);
                __nv_bfloat162 h2 = __floats2bfloat162_rn(f1.x, f1.y);
                __nv_bfloat162 h3 = __floats2bfloat162_rn(f1.z, f1.w);
                float2 e0 = __bfloat1622float2(h0), e1 = __bfloat1622float2(h1);
                float2 e2 = __bfloat1622float2(h2), e3 = __bfloat1622float2(h3);
                __nv_bfloat162 l0 = __floats2bfloat162_rn(f0.x - e0.x, f0.y - e0.y);
                __nv_bfloat162 l1 = __floats2bfloat162_rn(f0.z - e1.x, f0.w - e1.y);
                __nv_bfloat162 l2 = __floats2bfloat162_rn(f1.x - e2.x, f1.y - e2.y);
                __nv_bfloat162 l3 = __floats2bfloat162_rn(f1.z - e3.x, f1.w - e3.y);
                const uint32_t off = SW_OFF(lrow, kh + q);
                uint4 hv, lv;
                hv.x = *(uint32_t*)&h0; hv.y = *(uint32_t*)&h1;
                hv.z = *(uint32_t*)&h2; hv.w = *(uint32_t*)&h3;
                lv.x = *(uint32_t*)&l0; lv.y = *(uint32_t*)&l1;
                lv.z = *(uint32_t*)&l2; lv.w = *(uint32_t*)&l3;
                *(uint4*)(dsm + XH + off) = hv;
                *(uint4*)(dsm + XL + off) = lv;
            }
        }

        // ---- prefetch next tile's X (latency hidden behind MMA) ----------
        {
            const int grow = ntile * 128 + lrow;
            if (ntile < NTILES && grow < N) {
                const float4* xp = (const float4*)(X + (size_t)grow * DIM + lkoff);
                #pragma unroll
                for (int q = 0; q < 16; q++) pf[q] = xp[q];
            } else {
                #pragma unroll
                for (int q = 0; q < 16; q++) pf[q] = make_float4(0, 0, 0, 0);
            }
        }
        __syncthreads();

        for (int t = t0; t <= t1; ++t) {
            const uint32_t bhi = sbase + WB + (uint32_t)t * 65536u;
            const uint32_t blo = bhi + 32768u;

            float acc[2][8][4];
            #pragma unroll
            for (int i = 0; i < 2; i++)
                #pragma unroll
                for (int j = 0; j < 8; j++)
                    #pragma unroll
                    for (int p = 0; p < 4; p++) acc[i][j][p] = 0.f;

            #pragma unroll
            for (int ks = 0; ks < 8; ks++) {
                // ---- A fragments (hi & lo), live across both halves --------
                uint32_t ah[2][4], al[2][4];
                {
                    const int r    = lane & 7;
                    const int half = (lane >> 3) & 1;
                    const int ksel = lane >> 4;
                    const int akc  = ks * 2 + ksel;
                    #pragma unroll
                    for (int mt = 0; mt < 2; mt++) {
                        const uint32_t aoff = SW_OFF(m0 + mt * 16 + half * 8 + r, akc);
                        ldsm_x4(ah[mt][0], ah[mt][1], ah[mt][2], ah[mt][3],
                                sbase + XH + aoff);
                        ldsm_x4(al[mt][0], al[mt][1], al[mt][2], al[mt][3],
                                sbase + XL + aoff);
                    }
                }
                // ---- B in two 32-col halves: 16 B-regs reused --------------
                #pragma unroll
                for (int nh = 0; nh < 2; nh++) {
                    uint32_t bh[4][2], bl[4][2];
                    {
                        const int r    = lane & 7;
                        const int ksel = (lane >> 3) & 1;
                        const int jsel = lane >> 4;
                        const int bkc  = ks * 2 + ksel;
                        #pragma unroll
                        for (int jj = 0; jj < 2; jj++) {
                            const uint32_t boff =
                                SW_OFF(n0 + nh * 32 + jj * 16 + jsel * 8 + r, bkc);
                            uint32_t r0, r1, r2, r3;
                            ldsm_x4(r0, r1, r2, r3, bhi + boff);
                            bh[2 * jj][0] = r0;     bh[2 * jj][1] = r1;
                            bh[2 * jj + 1][0] = r2; bh[2 * jj + 1][1] = r3;
                            ldsm_x4(r0, r1, r2, r3, blo + boff);
                            bl[2 * jj][0] = r0;     bl[2 * jj][1] = r1;
                            bl[2 * jj + 1][0] = r2; bl[2 * jj + 1][1] = r3;
                        }
                    }
                    #pragma unroll
                    for (int mt = 0; mt < 2; mt++)
                        #pragma unroll
                        for (int nt = 0; nt < 4; nt++) {
                            float* a = acc[mt][nh * 4 + nt];
                            mma_bf16(a, ah[mt], bh[nt]);
                            mma_bf16(a, al[mt], bh[nt]);
                            mma_bf16(a, ah[mt], bl[nt]);
                        }
                }
            }

            // ---- epilogue: masked writeout --------------------------------
            {
                const int g  = lane >> 2;
                const int c2 = (lane & 3) * 2;
                #pragma unroll
                for (int mt = 0; mt < 2; mt++) {
                    #pragma unroll
                    for (int half = 0; half < 2; half++) {
                        const int grow = row0 + m0 + mt * 16 + half * 8 + g;
                        if (grow < N && (!mixed || ntype[grow] == t)) {
                            float2* yp = (float2*)(Y + (size_t)grow * DIM + n0 + c2);
                            #pragma unroll
                            for (int nt = 0; nt < 8; nt++)
                                yp[nt * 4] = make_float2(acc[mt][nt][half * 2],
                                                         acc[mt][nt][half * 2 + 1]);
                        }
                    }
                }
            }
        }

        tile = ntile;
    }
}

// ---------------------------------------------------------------------------
// Edge scatter-sum: g_h[dst[e],:] += g_v[src[e],:]. 8 edges per warp:
// uniform int4 index loads, 8 independent gathers (MLP=8), 8 RED.128/lane.
// (At the LTS traffic cap ~73us.)
// ---------------------------------------------------------------------------
__global__ __launch_bounds__(256) void scatter_kernel(
    const int* __restrict__ src, const int* __restrict__ dst)
{
    const int w    = (int)((blockIdx.x * (unsigned)blockDim.x + threadIdx.x) >> 5);
    const int lane = threadIdx.x & 31;
    const int4 s0 = __ldg((const int4*)src + w * 2);
    const int4 s1 = __ldg((const int4*)src + w * 2 + 1);
    const int4 d0 = __ldg((const int4*)dst + w * 2);
    const int4 d1 = __ldg((const int4*)dst + w * 2 + 1);
    const int s[8] = {s0.x, s0.y, s0.z, s0.w, s1.x, s1.y, s1.z, s1.w};
    const int d[8] = {d0.x, d0.y, d0.z, d0.w, d1.x, d1.y, d1.z, d1.w};

    float4 x[8];
    #pragma unroll
    for (int i = 0; i < 8; i++)
        x[i] = ((const float4*)(g_v + (size_t)s[i] * DIM))[lane];

    #pragma unroll
    for (int i = 0; i < 8; i++) {
        float* hd = g_h + (size_t)d[i] * DIM + lane * 4;
        asm volatile("red.global.add.v4.f32 [%0], {%1, %2, %3, %4};"
                     :: "l"(hd), "f"(x[i].x), "f"(x[i].y), "f"(x[i].z), "f"(x[i].w)
                     : "memory");
    }
}

// ---------------------------------------------------------------------------
extern "C" void kernel_launch(void* const* d_in, const int* in_sizes, int n_in,
                              void* d_out, int out_size)
{
    const float* x     = (const float*)d_in[0];
    const int*   ntype = (const int*)  d_in[1];
    const int*   src   = (const int*)  d_in[2];
    const int*   dst   = (const int*)  d_in[3];
    const float* W_v   = (const float*)d_in[4];
    const float* W_a   = (const float*)d_in[5];
    float*       out   = (float*)d_out;

    float *v_ptr, *h_ptr;
    cudaGetSymbolAddress((void**)&v_ptr, g_v);
    cudaGetSymbolAddress((void**)&h_ptr, g_h);

    const int N = N_NODES;
    const int SMEM_DYN = 196608;   // Xhi+Xlo (64K) + W both types hi/lo (128K)
    cudaFuncSetAttribute(gemm_mma_kernel,
                         cudaFuncAttributeMaxDynamicSharedMemorySize, SMEM_DYN);

    // prepack W (bf16 hi/lo swizzled SMEM images)
    prepack_kernel<<<(4 * 2 * 128 * 128 + 255) / 256, 256>>>(W_v, W_a);
    // v = typed_linear(x, W_v, ntype)  + fire-and-forget zero of g_h
    gemm_mma_kernel<<<148, 256, SMEM_DYN>>>(x, 0, 1, ntype, v_ptr, N);
    // h[dst] += v[src]  (8 edges/warp)
    scatter_kernel<<<N_EDGES / 8 / 8, 256>>>(src, dst);
    // out = typed_linear(h, W_a, ntype)
    gemm_mma_kernel<<<148, 256, SMEM_DYN>>>(h_ptr, 1, 0, ntype, out, N);
}

// round 13
// speedup vs baseline: 1.0270x; 1.0270x over previous
#include <cuda_runtime.h>
#include <cuda_bf16.h>
#include <cstdint>

#define N_NODES 100000
#define N_EDGES 800000
#define DIM 128
#define NTILES ((N_NODES + 127) / 128)

// ---------------------------------------------------------------------------
// Scratch (allocation-free rule: __device__ globals)
// ---------------------------------------------------------------------------
__device__ float g_v[N_NODES * DIM];
__device__ float g_h[N_NODES * DIM];
__device__ unsigned short g_Wmma[4][2 * 128 * 128];  // prepacked W images

// swizzled byte offset of (row, 16B-chunk kc) in a 256B-row tile
#define SW_OFF(row, kc) ((uint32_t)(row) * 256u + ((uint32_t)(((kc) ^ ((row) & 7))) << 4))

__device__ __forceinline__ uint32_t smem_u32(const void* p) {
    uint32_t a;
    asm("{ .reg .u64 t; cvta.to.shared.u64 t, %1; cvt.u32.u64 %0, t; }"
        : "=r"(a) : "l"(p));
    return a;
}
__device__ __forceinline__ void ldsm_x4(uint32_t& r0, uint32_t& r1, uint32_t& r2,
                                        uint32_t& r3, uint32_t addr) {
    asm volatile("ldmatrix.sync.aligned.m8n8.x4.shared.b16 {%0,%1,%2,%3}, [%4];"
                 : "=r"(r0), "=r"(r1), "=r"(r2), "=r"(r3) : "r"(addr));
}
__device__ __forceinline__ void mma_bf16(float* d, const uint32_t* a, const uint32_t* b) {
    asm volatile(
        "mma.sync.aligned.m16n8k16.row.col.f32.bf16.bf16.f32 "
        "{%0,%1,%2,%3}, {%4,%5,%6,%7}, {%8,%9}, {%0,%1,%2,%3};"
        : "+f"(d[0]), "+f"(d[1]), "+f"(d[2]), "+f"(d[3])
        : "r"(a[0]), "r"(a[1]), "r"(a[2]), "r"(a[3]), "r"(b[0]), "r"(b[1]));
}

// ---------------------------------------------------------------------------
// Prepack W -> g_Wmma: bf16 hi/lo, [n][k] rows (256B), XOR-swizzled 16B chunks
// ---------------------------------------------------------------------------
__global__ __launch_bounds__(256) void prepack_kernel(
    const float* __restrict__ W_v, const float* __restrict__ W_a)
{
    const int idx = blockIdx.x * 256 + threadIdx.x;
    if (idx >= 4 * 2 * 128 * 128) return;
    const int tile = idx >> 15;
    const int seg  = (idx >> 14) & 1;
    const int rem  = idx & 16383;
    const int n    = rem >> 7;
    const int k    = rem & 127;
    const int mat  = tile >> 1;
    const int typ  = tile & 1;

    const float* Wp = (mat ? W_a : W_v) + typ * DIM * DIM;
    const float w = Wp[k * DIM + n];
    __nv_bfloat16 hi = __float2bfloat16_rn(w);
    unsigned short out;
    if (seg == 0) {
        out = *(unsigned short*)&hi;
    } else {
        __nv_bfloat16 lo = __float2bfloat16_rn(w - __bfloat162float(hi));
        out = *(unsigned short*)&lo;
    }
    const uint32_t boff = SW_OFF(n, k >> 3) + (k & 7) * 2;
    g_Wmma[tile][seg * 16384 + (boff >> 1)] = out;
}

// ---------------------------------------------------------------------------
// Persistent typed tensor-core GEMM (FROZEN round-11 config): Y = X @ W[ntype]
// 256 threads (8 warps, 4m x 2n grid of 32x64 warp tiles). W (both types,
// hi/lo = 128KB) resident in SMEM; register prefetch of next tile's X.
// do_zero: gemm1 zeroes g_h with fire-and-forget stores behind compute.
// ---------------------------------------------------------------------------
__global__ __launch_bounds__(256) void gemm_mma_kernel(
    const float* __restrict__ X, int mat, int do_zero,
    const int* __restrict__ ntype, float* __restrict__ Y, int N)
{
    extern __shared__ char dsm[];
    const uint32_t sbase = smem_u32(dsm);
    const uint32_t XH = 0, XL = 32768, WB = 65536;   // W: +type*65536 +seg*32768

    const int tid  = threadIdx.x;
    const int wid  = tid >> 5;
    const int lane = tid & 31;

    // ---- fire-and-forget zero of g_h (gemm1 only) -------------------------
    if (do_zero) {
        float4* hp = (float4*)g_h;
        const int total  = N_NODES * DIM / 4;
        const int stride = gridDim.x * 256;
        for (int i = blockIdx.x * 256 + tid; i < total; i += stride)
            hp[i] = make_float4(0.f, 0.f, 0.f, 0.f);
    }

    // ---- load W (both types, hi+lo = 128KB) once -------------------------
    {
        const uint4* srcW0 = (const uint4*)g_Wmma[mat * 2 + 0];
        const uint4* srcW1 = (const uint4*)g_Wmma[mat * 2 + 1];
        uint4* dstW0 = (uint4*)(dsm + WB);
        uint4* dstW1 = (uint4*)(dsm + WB + 65536);
        #pragma unroll
        for (int i = 0; i < 16; i++) {
            dstW0[tid + 256 * i] = srcW0[tid + 256 * i];
            dstW1[tid + 256 * i] = srcW1[tid + 256 * i];
        }
    }

    const int m0 = (wid >> 1) * 32;
    const int n0 = (wid & 1) * 64;
    const int lrow  = tid >> 1;
    const int lkoff = (tid & 1) * 64;

    float4 pf[16];
    int tile = blockIdx.x;
    {
        const int grow = tile * 128 + lrow;
        if (tile < NTILES && grow < N) {
            const float4* xp = (const float4*)(X + (size_t)grow * DIM + lkoff);
            #pragma unroll
            for (int q = 0; q < 16; q++) pf[q] = xp[q];
        } else {
            #pragma unroll
            for (int q = 0; q < 16; q++) pf[q] = make_float4(0, 0, 0, 0);
        }
    }

    while (tile < NTILES) {
        const int row0 = tile * 128;
        const int lastRow = (row0 + 127 < N) ? (row0 + 127) : (N - 1);
        const int t0 = ntype[row0];
        const int t1 = ntype[lastRow];
        const bool mixed = (t0 != t1);
        const int ntile = tile + gridDim.x;

        __syncthreads();   // previous tile's compute done before X overwrite

        // ---- convert prefetched X -> bf16 hi/lo swizzled SMEM -------------
        {
            const int kh = (tid & 1) * 8;
            #pragma unroll
            for (int q = 0; q < 8; q++) {
                float4 f0 = pf[2 * q], f1 = pf[2 * q + 1];
                __nv_bfloat162 h0 = __floats2bfloat162_rn(f0.x, f0.y);
                __nv_bfloat162 h1 = __floats2bfloat162_rn(f0.z, f0.w);
                __nv_bfloat162 h2 = __floats2bfloat162_rn(f1.x, f1.y);
                __nv_bfloat162 h3 = __floats2bfloat162_rn(f1.z, f1.w);
                float2 e0 = __bfloat1622float2(h0), e1 = __bfloat1622float2(h1);
                float2 e2 = __bfloat1622float2(h2), e3 = __bfloat1622float2(h3);
                __nv_bfloat162 l0 = __floats2bfloat162_rn(f0.x - e0.x, f0.y - e0.y);
                __nv_bfloat162 l1 = __floats2bfloat162_rn(f0.z - e1.x, f0.w - e1.y);
                __nv_bfloat162 l2 = __floats2bfloat162_rn(f1.x - e2.x, f1.y - e2.y);
                __nv_bfloat162 l3 = __floats2bfloat162_rn(f1.z - e3.x, f1.w - e3.y);
                const uint32_t off = SW_OFF(lrow, kh + q);
                uint4 hv, lv;
                hv.x = *(uint32_t*)&h0; hv.y = *(uint32_t*)&h1;
                hv.z = *(uint32_t*)&h2; hv.w = *(uint32_t*)&h3;
                lv.x = *(uint32_t*)&l0; lv.y = *(uint32_t*)&l1;
                lv.z = *(uint32_t*)&l2; lv.w = *(uint32_t*)&l3;
                *(uint4*)(dsm + XH + off) = hv;
                *(uint4*)(dsm + XL + off) = lv;
            }
        }

        // ---- prefetch next tile's X (latency hidden behind MMA) ----------
        {
            const int grow = ntile * 128 + lrow;
            if (ntile < NTILES && grow < N) {
                const float4* xp = (const float4*)(X + (size_t)grow * DIM + lkoff);
                #pragma unroll
                for (int q = 0; q < 16; q++) pf[q] = xp[q];
            } else {
                #pragma unroll
                for (int q = 0; q < 16; q++) pf[q] = make_float4(0, 0, 0, 0);
            }
        }
        __syncthreads();

        for (int t = t0; t <= t1; ++t) {
            const uint32_t bhi = sbase + WB + (uint32_t)t * 65536u;
            const uint32_t blo = bhi + 32768u;

            float acc[2][8][4];
            #pragma unroll
            for (int i = 0; i < 2; i++)
                #pragma unroll
                for (int j = 0; j < 8; j++)
                    #pragma unroll
                    for (int p = 0; p < 4; p++) acc[i][j][p] = 0.f;

            #pragma unroll
            for (int ks = 0; ks < 8; ks++) {
                uint32_t ah[2][4], al[2][4];
                {
                    const int r    = lane & 7;
                    const int half = (lane >> 3) & 1;
                    const int ksel = lane >> 4;
                    const int akc  = ks * 2 + ksel;
                    #pragma unroll
                    for (int mt = 0; mt < 2; mt++) {
                        const uint32_t aoff = SW_OFF(m0 + mt * 16 + half * 8 + r, akc);
                        ldsm_x4(ah[mt][0], ah[mt][1], ah[mt][2], ah[mt][3],
                                sbase + XH + aoff);
                        ldsm_x4(al[mt][0], al[mt][1], al[mt][2], al[mt][3],
                                sbase + XL + aoff);
                    }
                }
                uint32_t bh[8][2], bl[8][2];
                {
                    const int r    = lane & 7;
                    const int ksel = (lane >> 3) & 1;
                    const int jsel = lane >> 4;
                    const int bkc  = ks * 2 + ksel;
                    #pragma unroll
                    for (int jj = 0; jj < 4; jj++) {
                        const uint32_t boff = SW_OFF(n0 + jj * 16 + jsel * 8 + r, bkc);
                        uint32_t r0, r1, r2, r3;
                        ldsm_x4(r0, r1, r2, r3, bhi + boff);
                        bh[2 * jj][0] = r0;     bh[2 * jj][1] = r1;
                        bh[2 * jj + 1][0] = r2; bh[2 * jj + 1][1] = r3;
                        ldsm_x4(r0, r1, r2, r3, blo + boff);
                        bl[2 * jj][0] = r0;     bl[2 * jj][1] = r1;
                        bl[2 * jj + 1][0] = r2; bl[2 * jj + 1][1] = r3;
                    }
                }
                #pragma unroll
                for (int mt = 0; mt < 2; mt++)
                    #pragma unroll
                    for (int nt = 0; nt < 8; nt++) {
                        mma_bf16(acc[mt][nt], ah[mt], bh[nt]);
                        mma_bf16(acc[mt][nt], al[mt], bh[nt]);
                        mma_bf16(acc[mt][nt], ah[mt], bl[nt]);
                    }
            }

            {
                const int g  = lane >> 2;
                const int c2 = (lane & 3) * 2;
                #pragma unroll
                for (int mt = 0; mt < 2; mt++) {
                    #pragma unroll
                    for (int half = 0; half < 2; half++) {
                        const int grow = row0 + m0 + mt * 16 + half * 8 + g;
                        if (grow < N && (!mixed || ntype[grow] == t)) {
                            float2* yp = (float2*)(Y + (size_t)grow * DIM + n0 + c2);
                            #pragma unroll
                            for (int nt = 0; nt < 8; nt++)
                                yp[nt * 4] = make_float2(acc[mt][nt][half * 2],
                                                         acc[mt][nt][half * 2 + 1]);
                        }
                    }
                }
            }
        }

        tile = ntile;
    }
}

// ---------------------------------------------------------------------------
// Edge scatter-sum: g_h[dst[e],:] += g_v[src[e],:]. 16 edges per warp
// (MLP=16): 4x int4 index loads, 16 independent gathers, 16 RED.128/lane.
// Grid-stride: 2 groups per block.
// ---------------------------------------------------------------------------
#define EPW 16                       // edges per warp per group
#define NWARPGROUPS (N_EDGES / EPW)  // 50000

__global__ __launch_bounds__(256) void scatter_kernel(
    const int* __restrict__ src, const int* __restrict__ dst)
{
    const int lane = threadIdx.x & 31;
    const int warp_in_blk = threadIdx.x >> 5;
    const int warps_per_it = gridDim.x * 8;

    for (int w = blockIdx.x * 8 + warp_in_blk; w < NWARPGROUPS; w += warps_per_it) {
        int s[EPW], d[EPW];
        #pragma unroll
        for (int g = 0; g < 4; g++) {
            const int4 sv = __ldg((const int4*)src + w * 4 + g);
            const int4 dv = __ldg((const int4*)dst + w * 4 + g);
            s[g * 4 + 0] = sv.x; s[g * 4 + 1] = sv.y;
            s[g * 4 + 2] = sv.z; s[g * 4 + 3] = sv.w;
            d[g * 4 + 0] = dv.x; d[g * 4 + 1] = dv.y;
            d[g * 4 + 2] = dv.z; d[g * 4 + 3] = dv.w;
        }

        float4 x[EPW];
        #pragma unroll
        for (int i = 0; i < EPW; i++)
            x[i] = ((const float4*)(g_v + (size_t)s[i] * DIM))[lane];

        #pragma unroll
        for (int i = 0; i < EPW; i++) {
            float* hd = g_h + (size_t)d[i] * DIM + lane * 4;
            asm volatile("red.global.add.v4.f32 [%0], {%1, %2, %3, %4};"
                         :: "l"(hd), "f"(x[i].x), "f"(x[i].y), "f"(x[i].z), "f"(x[i].w)
                         : "memory");
        }
    }
}

// ---------------------------------------------------------------------------
extern "C" void kernel_launch(void* const* d_in, const int* in_sizes, int n_in,
                              void* d_out, int out_size)
{
    const float* x     = (const float*)d_in[0];
    const int*   ntype = (const int*)  d_in[1];
    const int*   src   = (const int*)  d_in[2];
    const int*   dst   = (const int*)  d_in[3];
    const float* W_v   = (const float*)d_in[4];
    const float* W_a   = (const float*)d_in[5];
    float*       out   = (float*)d_out;

    float *v_ptr, *h_ptr;
    cudaGetSymbolAddress((void**)&v_ptr, g_v);
    cudaGetSymbolAddress((void**)&h_ptr, g_h);

    const int N = N_NODES;
    const int SMEM_DYN = 196608;   // Xhi+Xlo (64K) + W both types hi/lo (128K)
    cudaFuncSetAttribute(gemm_mma_kernel,
                         cudaFuncAttributeMaxDynamicSharedMemorySize, SMEM_DYN);

    // prepack W (bf16 hi/lo swizzled SMEM images)
    prepack_kernel<<<(4 * 2 * 128 * 128 + 255) / 256, 256>>>(W_v, W_a);
    // v = typed_linear(x, W_v, ntype)  + fire-and-forget zero of g_h
    gemm_mma_kernel<<<148, 256, SMEM_DYN>>>(x, 0, 1, ntype, v_ptr, N);
    // h[dst] += v[src]  (16 edges/warp, 2 groups/block)
    scatter_kernel<<<NWARPGROUPS / 8 / 2, 256>>>(src, dst);
    // out = typed_linear(h, W_a, ntype)
    gemm_mma_kernel<<<148, 256, SMEM_DYN>>>(h_ptr, 1, 0, ntype, out, N);
}

// round 14
// speedup vs baseline: 1.0887x; 1.0601x over previous
#include <cuda_runtime.h>
#include <cuda_bf16.h>
#include <cuda_fp16.h>
#include <cstdint>

#define N_NODES 100000
#define N_EDGES 800000
#define DIM 128
#define NTILES ((N_NODES + 127) / 128)

// ---------------------------------------------------------------------------
// Scratch (allocation-free rule: __device__ globals)
// ---------------------------------------------------------------------------
__device__ __half g_v[N_NODES * DIM];   // v in fp16: halves scatter gather bytes
__device__ float  g_h[N_NODES * DIM];   // h accumulated in fp32 (RED.ADD)
__device__ unsigned short g_Wmma[4][2 * 128 * 128];  // prepacked W images

// swizzled byte offset of (row, 16B-chunk kc) in a 256B-row tile
#define SW_OFF(row, kc) ((uint32_t)(row) * 256u + ((uint32_t)(((kc) ^ ((row) & 7))) << 4))

__device__ __forceinline__ uint32_t smem_u32(const void* p) {
    uint32_t a;
    asm("{ .reg .u64 t; cvta.to.shared.u64 t, %1; cvt.u32.u64 %0, t; }"
        : "=r"(a) : "l"(p));
    return a;
}
__device__ __forceinline__ void ldsm_x4(uint32_t& r0, uint32_t& r1, uint32_t& r2,
                                        uint32_t& r3, uint32_t addr) {
    asm volatile("ldmatrix.sync.aligned.m8n8.x4.shared.b16 {%0,%1,%2,%3}, [%4];"
                 : "=r"(r0), "=r"(r1), "=r"(r2), "=r"(r3) : "r"(addr));
}
__device__ __forceinline__ void mma_bf16(float* d, const uint32_t* a, const uint32_t* b) {
    asm volatile(
        "mma.sync.aligned.m16n8k16.row.col.f32.bf16.bf16.f32 "
        "{%0,%1,%2,%3}, {%4,%5,%6,%7}, {%8,%9}, {%0,%1,%2,%3};"
        : "+f"(d[0]), "+f"(d[1]), "+f"(d[2]), "+f"(d[3])
        : "r"(a[0]), "r"(a[1]), "r"(a[2]), "r"(a[3]), "r"(b[0]), "r"(b[1]));
}

// ---------------------------------------------------------------------------
// Prepack W -> g_Wmma: bf16 hi/lo, [n][k] rows (256B), XOR-swizzled 16B chunks
// ---------------------------------------------------------------------------
__global__ __launch_bounds__(256) void prepack_kernel(
    const float* __restrict__ W_v, const float* __restrict__ W_a)
{
    const int idx = blockIdx.x * 256 + threadIdx.x;
    if (idx >= 4 * 2 * 128 * 128) return;
    const int tile = idx >> 15;
    const int seg  = (idx >> 14) & 1;
    const int rem  = idx & 16383;
    const int n    = rem >> 7;
    const int k    = rem & 127;
    const int mat  = tile >> 1;
    const int typ  = tile & 1;

    const float* Wp = (mat ? W_a : W_v) + typ * DIM * DIM;
    const float w = Wp[k * DIM + n];
    __nv_bfloat16 hi = __float2bfloat16_rn(w);
    unsigned short out;
    if (seg == 0) {
        out = *(unsigned short*)&hi;
    } else {
        __nv_bfloat16 lo = __float2bfloat16_rn(w - __bfloat162float(hi));
        out = *(unsigned short*)&lo;
    }
    const uint32_t boff = SW_OFF(n, k >> 3) + (k & 7) * 2;
    g_Wmma[tile][seg * 16384 + (boff >> 1)] = out;
}

// ---------------------------------------------------------------------------
// Persistent typed tensor-core GEMM (FROZEN round-11 core): Y = X @ W[ntype]
// 256 threads (8 warps, 4m x 2n grid of 32x64 warp tiles). W (both types,
// hi/lo = 128KB) resident in SMEM; register prefetch of next tile's X.
// out_half: epilogue writes fp16 (for v); else fp32 (final output).
// do_zero: gemm1 zeroes g_h with fire-and-forget stores behind compute.
// ---------------------------------------------------------------------------
__global__ __launch_bounds__(256) void gemm_mma_kernel(
    const float* __restrict__ X, int mat, int do_zero, int out_half,
    const int* __restrict__ ntype, float* __restrict__ Yf, __half* __restrict__ Yh,
    int N)
{
    extern __shared__ char dsm[];
    const uint32_t sbase = smem_u32(dsm);
    const uint32_t XH = 0, XL = 32768, WB = 65536;   // W: +type*65536 +seg*32768

    const int tid  = threadIdx.x;
    const int wid  = tid >> 5;
    const int lane = tid & 31;

    // ---- fire-and-forget zero of g_h (gemm1 only) -------------------------
    if (do_zero) {
        float4* hp = (float4*)g_h;
        const int total  = N_NODES * DIM / 4;
        const int stride = gridDim.x * 256;
        for (int i = blockIdx.x * 256 + tid; i < total; i += stride)
            hp[i] = make_float4(0.f, 0.f, 0.f, 0.f);
    }

    // ---- load W (both types, hi+lo = 128KB) once -------------------------
    {
        const uint4* srcW0 = (const uint4*)g_Wmma[mat * 2 + 0];
        const uint4* srcW1 = (const uint4*)g_Wmma[mat * 2 + 1];
        uint4* dstW0 = (uint4*)(dsm + WB);
        uint4* dstW1 = (uint4*)(dsm + WB + 65536);
        #pragma unroll
        for (int i = 0; i < 16; i++) {
            dstW0[tid + 256 * i] = srcW0[tid + 256 * i];
            dstW1[tid + 256 * i] = srcW1[tid + 256 * i];
        }
    }

    const int m0 = (wid >> 1) * 32;
    const int n0 = (wid & 1) * 64;
    const int lrow  = tid >> 1;
    const int lkoff = (tid & 1) * 64;

    float4 pf[16];
    int tile = blockIdx.x;
    {
        const int grow = tile * 128 + lrow;
        if (tile < NTILES && grow < N) {
            const float4* xp = (const float4*)(X + (size_t)grow * DIM + lkoff);
            #pragma unroll
            for (int q = 0; q < 16; q++) pf[q] = xp[q];
        } else {
            #pragma unroll
            for (int q = 0; q < 16; q++) pf[q] = make_float4(0, 0, 0, 0);
        }
    }

    while (tile < NTILES) {
        const int row0 = tile * 128;
        const int lastRow = (row0 + 127 < N) ? (row0 + 127) : (N - 1);
        const int t0 = ntype[row0];
        const int t1 = ntype[lastRow];
        const bool mixed = (t0 != t1);
        const int ntile = tile + gridDim.x;

        __syncthreads();   // previous tile's compute done before X overwrite

        // ---- convert prefetched X -> bf16 hi/lo swizzled SMEM -------------
        {
            const int kh = (tid & 1) * 8;
            #pragma unroll
            for (int q = 0; q < 8; q++) {
                float4 f0 = pf[2 * q], f1 = pf[2 * q + 1];
                __nv_bfloat162 h0 = __floats2bfloat162_rn(f0.x, f0.y);
                __nv_bfloat162 h1 = __floats2bfloat162_rn(f0.z, f0.w);
                __nv_bfloat162 h2 = __floats2bfloat162_rn(f1.x, f1.y);
                __nv_bfloat162 h3 = __floats2bfloat162_rn(f1.z, f1.w);
                float2 e0 = __bfloat1622float2(h0), e1 = __bfloat1622float2(h1);
                float2 e2 = __bfloat1622float2(h2), e3 = __bfloat1622float2(h3);
                __nv_bfloat162 l0 = __floats2bfloat162_rn(f0.x - e0.x, f0.y - e0.y);
                __nv_bfloat162 l1 = __floats2bfloat162_rn(f0.z - e1.x, f0.w - e1.y);
                __nv_bfloat162 l2 = __floats2bfloat162_rn(f1.x - e2.x, f1.y - e2.y);
                __nv_bfloat162 l3 = __floats2bfloat162_rn(f1.z - e3.x, f1.w - e3.y);
                const uint32_t off = SW_OFF(lrow, kh + q);
                uint4 hv, lv;
                hv.x = *(uint32_t*)&h0; hv.y = *(uint32_t*)&h1;
                hv.z = *(uint32_t*)&h2; hv.w = *(uint32_t*)&h3;
                lv.x = *(uint32_t*)&l0; lv.y = *(uint32_t*)&l1;
                lv.z = *(uint32_t*)&l2; lv.w = *(uint32_t*)&l3;
                *(uint4*)(dsm + XH + off) = hv;
                *(uint4*)(dsm + XL + off) = lv;
            }
        }

        // ---- prefetch next tile's X (latency hidden behind MMA) ----------
        {
            const int grow = ntile * 128 + lrow;
            if (ntile < NTILES && grow < N) {
                const float4* xp = (const float4*)(X + (size_t)grow * DIM + lkoff);
                #pragma unroll
                for (int q = 0; q < 16; q++) pf[q] = xp[q];
            } else {
                #pragma unroll
                for (int q = 0; q < 16; q++) pf[q] = make_float4(0, 0, 0, 0);
            }
        }
        __syncthreads();

        for (int t = t0; t <= t1; ++t) {
            const uint32_t bhi = sbase + WB + (uint32_t)t * 65536u;
            const uint32_t blo = bhi + 32768u;

            float acc[2][8][4];
            #pragma unroll
            for (int i = 0; i < 2; i++)
                #pragma unroll
                for (int j = 0; j < 8; j++)
                    #pragma unroll
                    for (int p = 0; p < 4; p++) acc[i][j][p] = 0.f;

            #pragma unroll
            for (int ks = 0; ks < 8; ks++) {
                uint32_t ah[2][4], al[2][4];
                {
                    const int r    = lane & 7;
                    const int half = (lane >> 3) & 1;
                    const int ksel = lane >> 4;
                    const int akc  = ks * 2 + ksel;
                    #pragma unroll
                    for (int mt = 0; mt < 2; mt++) {
                        const uint32_t aoff = SW_OFF(m0 + mt * 16 + half * 8 + r, akc);
                        ldsm_x4(ah[mt][0], ah[mt][1], ah[mt][2], ah[mt][3],
                                sbase + XH + aoff);
                        ldsm_x4(al[mt][0], al[mt][1], al[mt][2], al[mt][3],
                                sbase + XL + aoff);
                    }
                }
                uint32_t bh[8][2], bl[8][2];
                {
                    const int r    = lane & 7;
                    const int ksel = (lane >> 3) & 1;
                    const int jsel = lane >> 4;
                    const int bkc  = ks * 2 + ksel;
                    #pragma unroll
                    for (int jj = 0; jj < 4; jj++) {
                        const uint32_t boff = SW_OFF(n0 + jj * 16 + jsel * 8 + r, bkc);
                        uint32_t r0, r1, r2, r3;
                        ldsm_x4(r0, r1, r2, r3, bhi + boff);
                        bh[2 * jj][0] = r0;     bh[2 * jj][1] = r1;
                        bh[2 * jj + 1][0] = r2; bh[2 * jj + 1][1] = r3;
                        ldsm_x4(r0, r1, r2, r3, blo + boff);
                        bl[2 * jj][0] = r0;     bl[2 * jj][1] = r1;
                        bl[2 * jj + 1][0] = r2; bl[2 * jj + 1][1] = r3;
                    }
                }
                #pragma unroll
                for (int mt = 0; mt < 2; mt++)
                    #pragma unroll
                    for (int nt = 0; nt < 8; nt++) {
                        mma_bf16(acc[mt][nt], ah[mt], bh[nt]);
                        mma_bf16(acc[mt][nt], al[mt], bh[nt]);
                        mma_bf16(acc[mt][nt], ah[mt], bl[nt]);
                    }
            }

            // ---- epilogue: masked writeout (fp16 for v, fp32 for out) ------
            {
                const int g  = lane >> 2;
                const int c2 = (lane & 3) * 2;
                #pragma unroll
                for (int mt = 0; mt < 2; mt++) {
                    #pragma unroll
                    for (int half = 0; half < 2; half++) {
                        const int grow = row0 + m0 + mt * 16 + half * 8 + g;
                        if (grow < N && (!mixed || ntype[grow] == t)) {
                            if (out_half) {
                                __half* yp = Yh + (size_t)grow * DIM + n0 + c2;
                                #pragma unroll
                                for (int nt = 0; nt < 8; nt++)
                                    *(__half2*)(yp + nt * 8) =
                                        __floats2half2_rn(acc[mt][nt][half * 2],
                                                          acc[mt][nt][half * 2 + 1]);
                            } else {
                                float2* yp = (float2*)(Yf + (size_t)grow * DIM + n0 + c2);
                                #pragma unroll
                                for (int nt = 0; nt < 8; nt++)
                                    yp[nt * 4] = make_float2(acc[mt][nt][half * 2],
                                                             acc[mt][nt][half * 2 + 1]);
                            }
                        }
                    }
                }
            }
        }

        tile = ntile;
    }
}

// ---------------------------------------------------------------------------
// Edge scatter-sum: g_h[dst[e],:] += v[src[e],:]. 8 edges per warp (MLP=8):
// uniform int4 index loads, 8 independent fp16 gathers (8B/lane), convert to
// fp32, 8 fire-and-forget RED.128/lane. Gather bytes halved vs fp32 v.
// ---------------------------------------------------------------------------
__global__ __launch_bounds__(256) void scatter_kernel(
    const int* __restrict__ src, const int* __restrict__ dst)
{
    const int w    = (int)((blockIdx.x * (unsigned)blockDim.x + threadIdx.x) >> 5);
    const int lane = threadIdx.x & 31;
    const int4 s0 = __ldg((const int4*)src + w * 2);
    const int4 s1 = __ldg((const int4*)src + w * 2 + 1);
    const int4 d0 = __ldg((const int4*)dst + w * 2);
    const int4 d1 = __ldg((const int4*)dst + w * 2 + 1);
    const int s[8] = {s0.x, s0.y, s0.z, s0.w, s1.x, s1.y, s1.z, s1.w};
    const int d[8] = {d0.x, d0.y, d0.z, d0.w, d1.x, d1.y, d1.z, d1.w};

    uint2 raw[8];
    #pragma unroll
    for (int i = 0; i < 8; i++)
        raw[i] = ((const uint2*)(g_v + (size_t)s[i] * DIM))[lane];

    #pragma unroll
    for (int i = 0; i < 8; i++) {
        const __half2 p0 = *(const __half2*)&raw[i].x;
        const __half2 p1 = *(const __half2*)&raw[i].y;
        const float2 f0 = __half22float2(p0);
        const float2 f1 = __half22float2(p1);
        float* hd = g_h + (size_t)d[i] * DIM + lane * 4;
        asm volatile("red.global.add.v4.f32 [%0], {%1, %2, %3, %4};"
                     :: "l"(hd), "f"(f0.x), "f"(f0.y), "f"(f1.x), "f"(f1.y)
                     : "memory");
    }
}

// ---------------------------------------------------------------------------
extern "C" void kernel_launch(void* const* d_in, const int* in_sizes, int n_in,
                              void* d_out, int out_size)
{
    const float* x     = (const float*)d_in[0];
    const int*   ntype = (const int*)  d_in[1];
    const int*   src   = (const int*)  d_in[2];
    const int*   dst   = (const int*)  d_in[3];
    const float* W_v   = (const float*)d_in[4];
    const float* W_a   = (const float*)d_in[5];
    float*       out   = (float*)d_out;

    __half* v_ptr;
    float*  h_ptr;
    cudaGetSymbolAddress((void**)&v_ptr, g_v);
    cudaGetSymbolAddress((void**)&h_ptr, g_h);

    const int N = N_NODES;
    const int SMEM_DYN = 196608;   // Xhi+Xlo (64K) + W both types hi/lo (128K)
    cudaFuncSetAttribute(gemm_mma_kernel,
                         cudaFuncAttributeMaxDynamicSharedMemorySize, SMEM_DYN);

    // prepack W (bf16 hi/lo swizzled SMEM images)
    prepack_kernel<<<(4 * 2 * 128 * 128 + 255) / 256, 256>>>(W_v, W_a);
    // v = typed_linear(x, W_v, ntype) -> fp16; + fire-and-forget zero of g_h
    gemm_mma_kernel<<<148, 256, SMEM_DYN>>>(x, 0, 1, 1, ntype, nullptr, v_ptr, N);
    // h[dst] += v[src]  (8 edges/warp, fp16 gather -> fp32 RED)
    scatter_kernel<<<N_EDGES / 8 / 8, 256>>>(src, dst);
    // out = typed_linear(h, W_a, ntype) -> fp32
    gemm_mma_kernel<<<148, 256, SMEM_DYN>>>(h_ptr, 1, 0, 0, ntype, out, nullptr, N);
}

// round 15
// speedup vs baseline: 1.2686x; 1.1652x over previous
#include <cuda_runtime.h>
#include <cuda_fp16.h>
#include <cstdint>

#define N_NODES 100000
#define N_EDGES 800000
#define DIM 128
#define NTILES ((N_NODES + 127) / 128)

// ---------------------------------------------------------------------------
// Scratch (allocation-free rule: __device__ globals)
// ---------------------------------------------------------------------------
__device__ __half g_v[N_NODES * DIM];   // v in fp16 (halves scatter gather bytes)
__device__ float  g_h[N_NODES * DIM];   // h accumulated in fp32 (RED.ADD)
__device__ unsigned short g_Wmma[4][128 * 128];  // prepacked fp16 W images (32KB each)

// swizzled byte offset of (row, 16B-chunk kc) in a 256B-row tile
#define SW_OFF(row, kc) ((uint32_t)(row) * 256u + ((uint32_t)(((kc) ^ ((row) & 7))) << 4))

__device__ __forceinline__ uint32_t smem_u32(const void* p) {
    uint32_t a;
    asm("{ .reg .u64 t; cvta.to.shared.u64 t, %1; cvt.u32.u64 %0, t; }"
        : "=r"(a) : "l"(p));
    return a;
}
__device__ __forceinline__ void ldsm_x4(uint32_t& r0, uint32_t& r1, uint32_t& r2,
                                        uint32_t& r3, uint32_t addr) {
    asm volatile("ldmatrix.sync.aligned.m8n8.x4.shared.b16 {%0,%1,%2,%3}, [%4];"
                 : "=r"(r0), "=r"(r1), "=r"(r2), "=r"(r3) : "r"(addr));
}
__device__ __forceinline__ void mma_f16(float* d, const uint32_t* a, const uint32_t* b) {
    asm volatile(
        "mma.sync.aligned.m16n8k16.row.col.f32.f16.f16.f32 "
        "{%0,%1,%2,%3}, {%4,%5,%6,%7}, {%8,%9}, {%0,%1,%2,%3};"
        : "+f"(d[0]), "+f"(d[1]), "+f"(d[2]), "+f"(d[3])
        : "r"(a[0]), "r"(a[1]), "r"(a[2]), "r"(a[3]), "r"(b[0]), "r"(b[1]));
}

// ---------------------------------------------------------------------------
// Prepack W -> g_Wmma: fp16, [n][k] rows (256B), XOR-swizzled 16B chunks
// ---------------------------------------------------------------------------
__global__ __launch_bounds__(256) void prepack_kernel(
    const float* __restrict__ W_v, const float* __restrict__ W_a)
{
    const int idx = blockIdx.x * 256 + threadIdx.x;   // 4 * 16384
    if (idx >= 4 * 128 * 128) return;
    const int tile = idx >> 14;
    const int rem  = idx & 16383;
    const int n    = rem >> 7;
    const int k    = rem & 127;
    const int mat  = tile >> 1;
    const int typ  = tile & 1;

    const float* Wp = (mat ? W_a : W_v) + typ * DIM * DIM;
    const __half h = __float2half_rn(Wp[k * DIM + n]);
    const uint32_t boff = SW_OFF(n, k >> 3) + (k & 7) * 2;
    g_Wmma[tile][boff >> 1] = *(const unsigned short*)&h;
}

// ---------------------------------------------------------------------------
// Persistent typed tensor-core GEMM, single-segment fp16: Y = X @ W[ntype]
// 256 threads (8 warps, 4m x 2n grid of 32x64 warp tiles), 2 CTAs/SM.
// SMEM: Xh (32KB) + W both types (64KB) = 96KB. grid = 296.
// out_half: epilogue writes fp16 (v); else fp32 (final output).
// do_zero: gemm1 zeroes g_h with fire-and-forget stores behind compute.
// ---------------------------------------------------------------------------
__global__ __launch_bounds__(256, 2) void gemm_mma_kernel(
    const float* __restrict__ X, int mat, int do_zero, int out_half,
    const int* __restrict__ ntype, float* __restrict__ Yf, __half* __restrict__ Yh,
    int N)
{
    extern __shared__ char dsm[];
    const uint32_t sbase = smem_u32(dsm);
    const uint32_t XH = 0, WB = 32768;   // W: +type*32768

    const int tid  = threadIdx.x;
    const int wid  = tid >> 5;
    const int lane = tid & 31;

    // ---- fire-and-forget zero of g_h (gemm1 only) -------------------------
    if (do_zero) {
        float4* hp = (float4*)g_h;
        const int total  = N_NODES * DIM / 4;
        const int stride = gridDim.x * 256;
        for (int i = blockIdx.x * 256 + tid; i < total; i += stride)
            hp[i] = make_float4(0.f, 0.f, 0.f, 0.f);
    }

    // ---- load W (both types, 64KB total) once -----------------------------
    {
        const uint4* srcW0 = (const uint4*)g_Wmma[mat * 2 + 0];
        const uint4* srcW1 = (const uint4*)g_Wmma[mat * 2 + 1];
        uint4* dstW0 = (uint4*)(dsm + WB);
        uint4* dstW1 = (uint4*)(dsm + WB + 32768);
        #pragma unroll
        for (int i = 0; i < 8; i++) {     // 2048 uint4 per image / 256 threads
            dstW0[tid + 256 * i] = srcW0[tid + 256 * i];
            dstW1[tid + 256 * i] = srcW1[tid + 256 * i];
        }
    }

    const int m0 = (wid >> 1) * 32;
    const int n0 = (wid & 1) * 64;
    const int lrow  = tid >> 1;          // 0..127
    const int lhalf = tid & 1;           // 64-col half

    for (int tile = blockIdx.x; tile < NTILES; tile += gridDim.x) {
        const int row0 = tile * 128;
        const int lastRow = (row0 + 127 < N) ? (row0 + 127) : (N - 1);
        const int t0 = ntype[row0];
        const int t1 = ntype[lastRow];
        const bool mixed = (t0 != t1);

        __syncthreads();   // previous tile's compute done before X overwrite

        // ---- load X fp32 -> convert fp16 -> swizzled SMEM (2 MLP-8 batches)
        {
            const int grow = row0 + lrow;
            const float4* xp = (const float4*)(X + (size_t)grow * DIM + lhalf * 64);
            #pragma unroll
            for (int b = 0; b < 2; b++) {
                float4 f[8];
                if (grow < N) {
                    #pragma unroll
                    for (int j = 0; j < 8; j++) f[j] = xp[b * 8 + j];
                } else {
                    #pragma unroll
                    for (int j = 0; j < 8; j++) f[j] = make_float4(0, 0, 0, 0);
                }
                #pragma unroll
                for (int q = 0; q < 4; q++) {
                    const float4 f0 = f[2 * q], f1 = f[2 * q + 1];
                    __half2 h0 = __floats2half2_rn(f0.x, f0.y);
                    __half2 h1 = __floats2half2_rn(f0.z, f0.w);
                    __half2 h2 = __floats2half2_rn(f1.x, f1.y);
                    __half2 h3 = __floats2half2_rn(f1.z, f1.w);
                    uint4 hv;
                    hv.x = *(uint32_t*)&h0; hv.y = *(uint32_t*)&h1;
                    hv.z = *(uint32_t*)&h2; hv.w = *(uint32_t*)&h3;
                    *(uint4*)(dsm + XH + SW_OFF(lrow, lhalf * 8 + b * 4 + q)) = hv;
                }
            }
        }
        __syncthreads();

        for (int t = t0; t <= t1; ++t) {
            const uint32_t bw = sbase + WB + (uint32_t)t * 32768u;

            float acc[2][8][4];
            #pragma unroll
            for (int i = 0; i < 2; i++)
                #pragma unroll
                for (int j = 0; j < 8; j++)
                    #pragma unroll
                    for (int p = 0; p < 4; p++) acc[i][j][p] = 0.f;

            #pragma unroll
            for (int ks = 0; ks < 8; ks++) {
                // ---- A fragments ------------------------------------------
                uint32_t ah[2][4];
                {
                    const int r    = lane & 7;
                    const int half = (lane >> 3) & 1;
                    const int ksel = lane >> 4;
                    const int akc  = ks * 2 + ksel;
                    #pragma unroll
                    for (int mt = 0; mt < 2; mt++) {
                        const uint32_t aoff = SW_OFF(m0 + mt * 16 + half * 8 + r, akc);
                        ldsm_x4(ah[mt][0], ah[mt][1], ah[mt][2], ah[mt][3],
                                sbase + XH + aoff);
                    }
                }
                // ---- B fragments (64 cols) --------------------------------
                uint32_t bh[8][2];
                {
                    const int r    = lane & 7;
                    const int ksel = (lane >> 3) & 1;
                    const int jsel = lane >> 4;
                    const int bkc  = ks * 2 + ksel;
                    #pragma unroll
                    for (int jj = 0; jj < 4; jj++) {
                        const uint32_t boff = SW_OFF(n0 + jj * 16 + jsel * 8 + r, bkc);
                        uint32_t r0, r1, r2, r3;
                        ldsm_x4(r0, r1, r2, r3, bw + boff);
                        bh[2 * jj][0] = r0;     bh[2 * jj][1] = r1;
                        bh[2 * jj + 1][0] = r2; bh[2 * jj + 1][1] = r3;
                    }
                }
                // ---- 16 MMAs ----------------------------------------------
                #pragma unroll
                for (int mt = 0; mt < 2; mt++)
                    #pragma unroll
                    for (int nt = 0; nt < 8; nt++)
                        mma_f16(acc[mt][nt], ah[mt], bh[nt]);
            }

            // ---- epilogue: masked writeout (fp16 for v, fp32 for out) ------
            {
                const int g  = lane >> 2;
                const int c2 = (lane & 3) * 2;
                #pragma unroll
                for (int mt = 0; mt < 2; mt++) {
                    #pragma unroll
                    for (int half = 0; half < 2; half++) {
                        const int grow = row0 + m0 + mt * 16 + half * 8 + g;
                        if (grow < N && (!mixed || ntype[grow] == t)) {
                            if (out_half) {
                                __half* yp = Yh + (size_t)grow * DIM + n0 + c2;
                                #pragma unroll
                                for (int nt = 0; nt < 8; nt++)
                                    *(__half2*)(yp + nt * 8) =
                                        __floats2half2_rn(acc[mt][nt][half * 2],
                                                          acc[mt][nt][half * 2 + 1]);
                            } else {
                                float2* yp = (float2*)(Yf + (size_t)grow * DIM + n0 + c2);
                                #pragma unroll
                                for (int nt = 0; nt < 8; nt++)
                                    yp[nt * 4] = make_float2(acc[mt][nt][half * 2],
                                                             acc[mt][nt][half * 2 + 1]);
                            }
                        }
                    }
                }
            }
        }
    }
}

// ---------------------------------------------------------------------------
// Edge scatter-sum: g_h[dst[e],:] += v[src[e],:]. 8 edges per warp (MLP=8):
// uniform int4 index loads, 8 independent fp16 gathers (8B/lane), convert to
// fp32, 8 fire-and-forget RED.128/lane.
// ---------------------------------------------------------------------------
__global__ __launch_bounds__(256) void scatter_kernel(
    const int* __restrict__ src, const int* __restrict__ dst)
{
    const int w    = (int)((blockIdx.x * (unsigned)blockDim.x + threadIdx.x) >> 5);
    const int lane = threadIdx.x & 31;
    const int4 s0 = __ldg((const int4*)src + w * 2);
    const int4 s1 = __ldg((const int4*)src + w * 2 + 1);
    const int4 d0 = __ldg((const int4*)dst + w * 2);
    const int4 d1 = __ldg((const int4*)dst + w * 2 + 1);
    const int s[8] = {s0.x, s0.y, s0.z, s0.w, s1.x, s1.y, s1.z, s1.w};
    const int d[8] = {d0.x, d0.y, d0.z, d0.w, d1.x, d1.y, d1.z, d1.w};

    uint2 raw[8];
    #pragma unroll
    for (int i = 0; i < 8; i++)
        raw[i] = ((const uint2*)(g_v + (size_t)s[i] * DIM))[lane];

    #pragma unroll
    for (int i = 0; i < 8; i++) {
        const __half2 p0 = *(const __half2*)&raw[i].x;
        const __half2 p1 = *(const __half2*)&raw[i].y;
        const float2 f0 = __half22float2(p0);
        const float2 f1 = __half22float2(p1);
        float* hd = g_h + (size_t)d[i] * DIM + lane * 4;
        asm volatile("red.global.add.v4.f32 [%0], {%1, %2, %3, %4};"
                     :: "l"(hd), "f"(f0.x), "f"(f0.y), "f"(f1.x), "f"(f1.y)
                     : "memory");
    }
}

// ---------------------------------------------------------------------------
extern "C" void kernel_launch(void* const* d_in, const int* in_sizes, int n_in,
                              void* d_out, int out_size)
{
    const float* x     = (const float*)d_in[0];
    const int*   ntype = (const int*)  d_in[1];
    const int*   src   = (const int*)  d_in[2];
    const int*   dst   = (const int*)  d_in[3];
    const float* W_v   = (const float*)d_in[4];
    const float* W_a   = (const float*)d_in[5];
    float*       out   = (float*)d_out;

    __half* v_ptr;
    float*  h_ptr;
    cudaGetSymbolAddress((void**)&v_ptr, g_v);
    cudaGetSymbolAddress((void**)&h_ptr, g_h);

    const int N = N_NODES;
    const int SMEM_DYN = 98304;   // Xh (32K) + W both types (64K)
    cudaFuncSetAttribute(gemm_mma_kernel,
                         cudaFuncAttributeMaxDynamicSharedMemorySize, SMEM_DYN);

    // prepack W (fp16 swizzled SMEM images)
    prepack_kernel<<<(4 * 128 * 128 + 255) / 256, 256>>>(W_v, W_a);
    // v = typed_linear(x, W_v, ntype) -> fp16; + fire-and-forget zero of g_h
    gemm_mma_kernel<<<296, 256, SMEM_DYN>>>(x, 0, 1, 1, ntype, nullptr, v_ptr, N);
    // h[dst] += v[src]  (8 edges/warp, fp16 gather -> fp32 RED)
    scatter_kernel<<<N_EDGES / 8 / 8, 256>>>(src, dst);
    // out = typed_linear(h, W_a, ntype) -> fp32
    gemm_mma_kernel<<<296, 256, SMEM_DYN>>>(h_ptr, 1, 0, 0, ntype, out, nullptr, N);
}

// round 16
// speedup vs baseline: 1.2830x; 1.0114x over previous
#include <cuda_runtime.h>
#include <cuda_fp16.h>
#include <cstdint>

#define N_NODES 100000
#define N_EDGES 800000
#define DIM 128
#define NTILES ((N_NODES + 127) / 128)

// ---------------------------------------------------------------------------
// Scratch (allocation-free rule: __device__ globals)
// ---------------------------------------------------------------------------
__device__ __half g_v[N_NODES * DIM];   // v in fp16 (halves scatter gather bytes)
__device__ float  g_h[N_NODES * DIM];   // h accumulated in fp32 (RED.ADD)
__device__ unsigned short g_Wmma[4][128 * 128];  // prepacked fp16 W images (32KB each)

// swizzled byte offset of (row, 16B-chunk kc) in a 256B-row tile
#define SW_OFF(row, kc) ((uint32_t)(row) * 256u + ((uint32_t)(((kc) ^ ((row) & 7))) << 4))

__device__ __forceinline__ uint32_t smem_u32(const void* p) {
    uint32_t a;
    asm("{ .reg .u64 t; cvta.to.shared.u64 t, %1; cvt.u32.u64 %0, t; }"
        : "=r"(a) : "l"(p));
    return a;
}
__device__ __forceinline__ void ldsm_x4(uint32_t& r0, uint32_t& r1, uint32_t& r2,
                                        uint32_t& r3, uint32_t addr) {
    asm volatile("ldmatrix.sync.aligned.m8n8.x4.shared.b16 {%0,%1,%2,%3}, [%4];"
                 : "=r"(r0), "=r"(r1), "=r"(r2), "=r"(r3) : "r"(addr));
}
__device__ __forceinline__ void mma_f16(float* d, const uint32_t* a, const uint32_t* b) {
    asm volatile(
        "mma.sync.aligned.m16n8k16.row.col.f32.f16.f16.f32 "
        "{%0,%1,%2,%3}, {%4,%5,%6,%7}, {%8,%9}, {%0,%1,%2,%3};"
        : "+f"(d[0]), "+f"(d[1]), "+f"(d[2]), "+f"(d[3])
        : "r"(a[0]), "r"(a[1]), "r"(a[2]), "r"(a[3]), "r"(b[0]), "r"(b[1]));
}

// ---------------------------------------------------------------------------
// Prepack W -> g_Wmma: fp16, [n][k] rows (256B), XOR-swizzled 16B chunks
// ---------------------------------------------------------------------------
__global__ __launch_bounds__(256) void prepack_kernel(
    const float* __restrict__ W_v, const float* __restrict__ W_a)
{
    const int idx = blockIdx.x * 256 + threadIdx.x;   // 4 * 16384
    if (idx >= 4 * 128 * 128) return;
    const int tile = idx >> 14;
    const int rem  = idx & 16383;
    const int n    = rem >> 7;
    const int k    = rem & 127;
    const int mat  = tile >> 1;
    const int typ  = tile & 1;

    const float* Wp = (mat ? W_a : W_v) + typ * DIM * DIM;
    const __half h = __float2half_rn(Wp[k * DIM + n]);
    const uint32_t boff = SW_OFF(n, k >> 3) + (k & 7) * 2;
    g_Wmma[tile][boff >> 1] = *(const unsigned short*)&h;
}

// ---------------------------------------------------------------------------
// Persistent typed tensor-core GEMM, single-segment fp16: Y = X @ W[ntype]
// 256 threads (8 warps, 4m x 2n grid of 32x64 warp tiles), 2 CTAs/SM.
// SMEM: Xh (32KB) + W both types (64KB) = 96KB. grid = 296.
// X load is a single MLP-16 LDG burst (f[16] overlays acc's registers —
// acc is not live during the convert phase), halving exposed load rounds.
// out_half: epilogue writes fp16 (v); else fp32 (final output).
// do_zero: gemm1 zeroes g_h with fire-and-forget stores behind compute.
// ---------------------------------------------------------------------------
__global__ __launch_bounds__(256, 2) void gemm_mma_kernel(
    const float* __restrict__ X, int mat, int do_zero, int out_half,
    const int* __restrict__ ntype, float* __restrict__ Yf, __half* __restrict__ Yh,
    int N)
{
    extern __shared__ char dsm[];
    const uint32_t sbase = smem_u32(dsm);
    const uint32_t XH = 0, WB = 32768;   // W: +type*32768

    const int tid  = threadIdx.x;
    const int wid  = tid >> 5;
    const int lane = tid & 31;

    // ---- fire-and-forget zero of g_h (gemm1 only) -------------------------
    if (do_zero) {
        float4* hp = (float4*)g_h;
        const int total  = N_NODES * DIM / 4;
        const int stride = gridDim.x * 256;
        for (int i = blockIdx.x * 256 + tid; i < total; i += stride)
            hp[i] = make_float4(0.f, 0.f, 0.f, 0.f);
    }

    // ---- load W (both types, 64KB total) once -----------------------------
    {
        const uint4* srcW0 = (const uint4*)g_Wmma[mat * 2 + 0];
        const uint4* srcW1 = (const uint4*)g_Wmma[mat * 2 + 1];
        uint4* dstW0 = (uint4*)(dsm + WB);
        uint4* dstW1 = (uint4*)(dsm + WB + 32768);
        #pragma unroll
        for (int i = 0; i < 8; i++) {     // 2048 uint4 per image / 256 threads
            dstW0[tid + 256 * i] = srcW0[tid + 256 * i];
            dstW1[tid + 256 * i] = srcW1[tid + 256 * i];
        }
    }

    const int m0 = (wid >> 1) * 32;
    const int n0 = (wid & 1) * 64;
    const int lrow  = tid >> 1;          // 0..127
    const int lhalf = tid & 1;           // 64-col half

    for (int tile = blockIdx.x; tile < NTILES; tile += gridDim.x) {
        const int row0 = tile * 128;
        const int lastRow = (row0 + 127 < N) ? (row0 + 127) : (N - 1);
        const int t0 = ntype[row0];
        const int t1 = ntype[lastRow];
        const bool mixed = (t0 != t1);

        __syncthreads();   // previous tile's compute done before X overwrite

        // ---- load X fp32 (one MLP-16 burst) -> fp16 -> swizzled SMEM ------
        {
            const int grow = row0 + lrow;
            const float4* xp = (const float4*)(X + (size_t)grow * DIM + lhalf * 64);
            float4 f[16];
            if (grow < N) {
                #pragma unroll
                for (int j = 0; j < 16; j++) f[j] = xp[j];
            } else {
                #pragma unroll
                for (int j = 0; j < 16; j++) f[j] = make_float4(0, 0, 0, 0);
            }
            #pragma unroll
            for (int q = 0; q < 8; q++) {
                const float4 f0 = f[2 * q], f1 = f[2 * q + 1];
                __half2 h0 = __floats2half2_rn(f0.x, f0.y);
                __half2 h1 = __floats2half2_rn(f0.z, f0.w);
                __half2 h2 = __floats2half2_rn(f1.x, f1.y);
                __half2 h3 = __floats2half2_rn(f1.z, f1.w);
                uint4 hv;
                hv.x = *(uint32_t*)&h0; hv.y = *(uint32_t*)&h1;
                hv.z = *(uint32_t*)&h2; hv.w = *(uint32_t*)&h3;
                *(uint4*)(dsm + XH + SW_OFF(lrow, lhalf * 8 + q)) = hv;
            }
        }
        __syncthreads();

        for (int t = t0; t <= t1; ++t) {
            const uint32_t bw = sbase + WB + (uint32_t)t * 32768u;

            float acc[2][8][4];
            #pragma unroll
            for (int i = 0; i < 2; i++)
                #pragma unroll
                for (int j = 0; j < 8; j++)
                    #pragma unroll
                    for (int p = 0; p < 4; p++) acc[i][j][p] = 0.f;

            #pragma unroll
            for (int ks = 0; ks < 8; ks++) {
                // ---- A fragments ------------------------------------------
                uint32_t ah[2][4];
                {
                    const int r    = lane & 7;
                    const int half = (lane >> 3) & 1;
                    const int ksel = lane >> 4;
                    const int akc  = ks * 2 + ksel;
                    #pragma unroll
                    for (int mt = 0; mt < 2; mt++) {
                        const uint32_t aoff = SW_OFF(m0 + mt * 16 + half * 8 + r, akc);
                        ldsm_x4(ah[mt][0], ah[mt][1], ah[mt][2], ah[mt][3],
                                sbase + XH + aoff);
                    }
                }
                // ---- B fragments (64 cols) --------------------------------
                uint32_t bh[8][2];
                {
                    const int r    = lane & 7;
                    const int ksel = (lane >> 3) & 1;
                    const int jsel = lane >> 4;
                    const int bkc  = ks * 2 + ksel;
                    #pragma unroll
                    for (int jj = 0; jj < 4; jj++) {
                        const uint32_t boff = SW_OFF(n0 + jj * 16 + jsel * 8 + r, bkc);
                        uint32_t r0, r1, r2, r3;
                        ldsm_x4(r0, r1, r2, r3, bw + boff);
                        bh[2 * jj][0] = r0;     bh[2 * jj][1] = r1;
                        bh[2 * jj + 1][0] = r2; bh[2 * jj + 1][1] = r3;
                    }
                }
                // ---- 16 MMAs ----------------------------------------------
                #pragma unroll
                for (int mt = 0; mt < 2; mt++)
                    #pragma unroll
                    for (int nt = 0; nt < 8; nt++)
                        mma_f16(acc[mt][nt], ah[mt], bh[nt]);
            }

            // ---- epilogue: masked writeout (fp16 for v, fp32 for out) ------
            {
                const int g  = lane >> 2;
                const int c2 = (lane & 3) * 2;
                #pragma unroll
                for (int mt = 0; mt < 2; mt++) {
                    #pragma unroll
                    for (int half = 0; half < 2; half++) {
                        const int grow = row0 + m0 + mt * 16 + half * 8 + g;
                        if (grow < N && (!mixed || ntype[grow] == t)) {
                            if (out_half) {
                                __half* yp = Yh + (size_t)grow * DIM + n0 + c2;
                                #pragma unroll
                                for (int nt = 0; nt < 8; nt++)
                                    *(__half2*)(yp + nt * 8) =
                                        __floats2half2_rn(acc[mt][nt][half * 2],
                                                          acc[mt][nt][half * 2 + 1]);
                            } else {
                                float2* yp = (float2*)(Yf + (size_t)grow * DIM + n0 + c2);
                                #pragma unroll
                                for (int nt = 0; nt < 8; nt++)
                                    yp[nt * 4] = make_float2(acc[mt][nt][half * 2],
                                                             acc[mt][nt][half * 2 + 1]);
                            }
                        }
                    }
                }
            }
        }
    }
}

// ---------------------------------------------------------------------------
// Edge scatter-sum: g_h[dst[e],:] += v[src[e],:]. 8 edges per warp (MLP=8):
// uniform int4 index loads, 8 independent fp16 gathers (8B/lane), convert to
// fp32, 8 fire-and-forget RED.128/lane. (At LTS traffic cap — frozen.)
// ---------------------------------------------------------------------------
__global__ __launch_bounds__(256) void scatter_kernel(
    const int* __restrict__ src, const int* __restrict__ dst)
{
    const int w    = (int)((blockIdx.x * (unsigned)blockDim.x + threadIdx.x) >> 5);
    const int lane = threadIdx.x & 31;
    const int4 s0 = __ldg((const int4*)src + w * 2);
    const int4 s1 = __ldg((const int4*)src + w * 2 + 1);
    const int4 d0 = __ldg((const int4*)dst + w * 2);
    const int4 d1 = __ldg((const int4*)dst + w * 2 + 1);
    const int s[8] = {s0.x, s0.y, s0.z, s0.w, s1.x, s1.y, s1.z, s1.w};
    const int d[8] = {d0.x, d0.y, d0.z, d0.w, d1.x, d1.y, d1.z, d1.w};

    uint2 raw[8];
    #pragma unroll
    for (int i = 0; i < 8; i++)
        raw[i] = ((const uint2*)(g_v + (size_t)s[i] * DIM))[lane];

    #pragma unroll
    for (int i = 0; i < 8; i++) {
        const __half2 p0 = *(const __half2*)&raw[i].x;
        const __half2 p1 = *(const __half2*)&raw[i].y;
        const float2 f0 = __half22float2(p0);
        const float2 f1 = __half22float2(p1);
        float* hd = g_h + (size_t)d[i] * DIM + lane * 4;
        asm volatile("red.global.add.v4.f32 [%0], {%1, %2, %3, %4};"
                     :: "l"(hd), "f"(f0.x), "f"(f0.y), "f"(f1.x), "f"(f1.y)
                     : "memory");
    }
}

// ---------------------------------------------------------------------------
extern "C" void kernel_launch(void* const* d_in, const int* in_sizes, int n_in,
                              void* d_out, int out_size)
{
    const float* x     = (const float*)d_in[0];
    const int*   ntype = (const int*)  d_in[1];
    const int*   src   = (const int*)  d_in[2];
    const int*   dst   = (const int*)  d_in[3];
    const float* W_v   = (const float*)d_in[4];
    const float* W_a   = (const float*)d_in[5];
    float*       out   = (float*)d_out;

    __half* v_ptr;
    float*  h_ptr;
    cudaGetSymbolAddress((void**)&v_ptr, g_v);
    cudaGetSymbolAddress((void**)&h_ptr, g_h);

    const int N = N_NODES;
    const int SMEM_DYN = 98304;   // Xh (32K) + W both types (64K)
    cudaFuncSetAttribute(gemm_mma_kernel,
                         cudaFuncAttributeMaxDynamicSharedMemorySize, SMEM_DYN);

    // prepack W (fp16 swizzled SMEM images)
    prepack_kernel<<<(4 * 128 * 128 + 255) / 256, 256>>>(W_v, W_a);
    // v = typed_linear(x, W_v, ntype) -> fp16; + fire-and-forget zero of g_h
    gemm_mma_kernel<<<296, 256, SMEM_DYN>>>(x, 0, 1, 1, ntype, nullptr, v_ptr, N);
    // h[dst] += v[src]  (8 edges/warp, fp16 gather -> fp32 RED)
    scatter_kernel<<<N_EDGES / 8 / 8, 256>>>(src, dst);
    // out = typed_linear(h, W_a, ntype) -> fp32
    gemm_mma_kernel<<<296, 256, SMEM_DYN>>>(h_ptr, 1, 0, 0, ntype, out, nullptr, N);
}

// round 17
// speedup vs baseline: 1.7170x; 1.3383x over previous
#include <cuda_runtime.h>
#include <cuda_fp16.h>
#include <cstdint>

#define N_NODES 100000
#define N_EDGES 800000
#define DIM 128
#define NTILES ((N_NODES + 127) / 128)

// ---------------------------------------------------------------------------
// Scratch (allocation-free rule: __device__ globals)
// ---------------------------------------------------------------------------
__device__ __half g_v[N_NODES * DIM];   // v in fp16
__device__ __half g_h[N_NODES * DIM];   // h accumulated in fp16 (RED.v2.f16x2)
__device__ unsigned short g_Wmma[4][128 * 128];  // prepacked fp16 W images

// swizzled byte offset of (row, 16B-chunk kc) in a 256B-row tile
#define SW_OFF(row, kc) ((uint32_t)(row) * 256u + ((uint32_t)(((kc) ^ ((row) & 7))) << 4))

__device__ __forceinline__ uint32_t smem_u32(const void* p) {
    uint32_t a;
    asm("{ .reg .u64 t; cvta.to.shared.u64 t, %1; cvt.u32.u64 %0, t; }"
        : "=r"(a) : "l"(p));
    return a;
}
__device__ __forceinline__ void ldsm_x4(uint32_t& r0, uint32_t& r1, uint32_t& r2,
                                        uint32_t& r3, uint32_t addr) {
    asm volatile("ldmatrix.sync.aligned.m8n8.x4.shared.b16 {%0,%1,%2,%3}, [%4];"
                 : "=r"(r0), "=r"(r1), "=r"(r2), "=r"(r3) : "r"(addr));
}
__device__ __forceinline__ void mma_f16(float* d, const uint32_t* a, const uint32_t* b) {
    asm volatile(
        "mma.sync.aligned.m16n8k16.row.col.f32.f16.f16.f32 "
        "{%0,%1,%2,%3}, {%4,%5,%6,%7}, {%8,%9}, {%0,%1,%2,%3};"
        : "+f"(d[0]), "+f"(d[1]), "+f"(d[2]), "+f"(d[3])
        : "r"(a[0]), "r"(a[1]), "r"(a[2]), "r"(a[3]), "r"(b[0]), "r"(b[1]));
}

// ---------------------------------------------------------------------------
// Prepack W -> g_Wmma: fp16, [n][k] rows (256B), XOR-swizzled 16B chunks
// ---------------------------------------------------------------------------
__global__ __launch_bounds__(256) void prepack_kernel(
    const float* __restrict__ W_v, const float* __restrict__ W_a)
{
    const int idx = blockIdx.x * 256 + threadIdx.x;   // 4 * 16384
    if (idx >= 4 * 128 * 128) return;
    const int tile = idx >> 14;
    const int rem  = idx & 16383;
    const int n    = rem >> 7;
    const int k    = rem & 127;
    const int mat  = tile >> 1;
    const int typ  = tile & 1;

    const float* Wp = (mat ? W_a : W_v) + typ * DIM * DIM;
    const __half h = __float2half_rn(Wp[k * DIM + n]);
    const uint32_t boff = SW_OFF(n, k >> 3) + (k & 7) * 2;
    g_Wmma[tile][boff >> 1] = *(const unsigned short*)&h;
}

// ---------------------------------------------------------------------------
// Persistent typed tensor-core GEMM, single-segment fp16: Y = X @ W[ntype]
// 256 threads (8 warps, 4m x 2n grid of 32x64 warp tiles), 2 CTAs/SM.
// SMEM: Xh (32KB) + W both types (64KB) = 96KB. grid = 296.
// in_half: X source is fp16 (h) -> pure copy into swizzled smem, no cvt.
// out_half: epilogue writes fp16 (v); else fp32 (final output).
// do_zero: gemm1 zeroes fp16 g_h with fire-and-forget stores behind compute.
// ---------------------------------------------------------------------------
__global__ __launch_bounds__(256, 2) void gemm_mma_kernel(
    const float* __restrict__ Xf, const __half* __restrict__ Xh_in,
    int mat, int do_zero, int in_half, int out_half,
    const int* __restrict__ ntype, float* __restrict__ Yf, __half* __restrict__ Yh,
    int N)
{
    extern __shared__ char dsm[];
    const uint32_t sbase = smem_u32(dsm);
    const uint32_t XH = 0, WB = 32768;   // W: +type*32768

    const int tid  = threadIdx.x;
    const int wid  = tid >> 5;
    const int lane = tid & 31;

    // ---- fire-and-forget zero of g_h (gemm1 only; fp16 -> 25.6MB) ---------
    if (do_zero) {
        uint4* hp = (uint4*)g_h;
        const int total  = N_NODES * DIM * 2 / 16;
        const int stride = gridDim.x * 256;
        const uint4 z = make_uint4(0u, 0u, 0u, 0u);
        for (int i = blockIdx.x * 256 + tid; i < total; i += stride)
            hp[i] = z;
    }

    // ---- load W (both types, 64KB total) once -----------------------------
    {
        const uint4* srcW0 = (const uint4*)g_Wmma[mat * 2 + 0];
        const uint4* srcW1 = (const uint4*)g_Wmma[mat * 2 + 1];
        uint4* dstW0 = (uint4*)(dsm + WB);
        uint4* dstW1 = (uint4*)(dsm + WB + 32768);
        #pragma unroll
        for (int i = 0; i < 8; i++) {
            dstW0[tid + 256 * i] = srcW0[tid + 256 * i];
            dstW1[tid + 256 * i] = srcW1[tid + 256 * i];
        }
    }

    const int m0 = (wid >> 1) * 32;
    const int n0 = (wid & 1) * 64;
    const int lrow  = tid >> 1;          // 0..127
    const int lhalf = tid & 1;           // 64-col half

    for (int tile = blockIdx.x; tile < NTILES; tile += gridDim.x) {
        const int row0 = tile * 128;
        const int lastRow = (row0 + 127 < N) ? (row0 + 127) : (N - 1);
        const int t0 = ntype[row0];
        const int t1 = ntype[lastRow];
        const bool mixed = (t0 != t1);

        __syncthreads();   // previous tile's compute done before X overwrite

        const int grow = row0 + lrow;
        if (in_half) {
            // ---- fp16 X: straight copy into swizzled SMEM (one MLP-8) -----
            const uint4* xp = (const uint4*)(Xh_in + (size_t)grow * DIM + lhalf * 64);
            uint4 v[8];
            if (grow < N) {
                #pragma unroll
                for (int j = 0; j < 8; j++) v[j] = xp[j];
            } else {
                #pragma unroll
                for (int j = 0; j < 8; j++) v[j] = make_uint4(0u, 0u, 0u, 0u);
            }
            #pragma unroll
            for (int q = 0; q < 8; q++)
                *(uint4*)(dsm + XH + SW_OFF(lrow, lhalf * 8 + q)) = v[q];
        } else {
            // ---- fp32 X: one MLP-16 burst -> fp16 -> swizzled SMEM --------
            const float4* xp = (const float4*)(Xf + (size_t)grow * DIM + lhalf * 64);
            float4 f[16];
            if (grow < N) {
                #pragma unroll
                for (int j = 0; j < 16; j++) f[j] = xp[j];
            } else {
                #pragma unroll
                for (int j = 0; j < 16; j++) f[j] = make_float4(0, 0, 0, 0);
            }
            #pragma unroll
            for (int q = 0; q < 8; q++) {
                const float4 f0 = f[2 * q], f1 = f[2 * q + 1];
                __half2 h0 = __floats2half2_rn(f0.x, f0.y);
                __half2 h1 = __floats2half2_rn(f0.z, f0.w);
                __half2 h2 = __floats2half2_rn(f1.x, f1.y);
                __half2 h3 = __floats2half2_rn(f1.z, f1.w);
                uint4 hv;
                hv.x = *(uint32_t*)&h0; hv.y = *(uint32_t*)&h1;
                hv.z = *(uint32_t*)&h2; hv.w = *(uint32_t*)&h3;
                *(uint4*)(dsm + XH + SW_OFF(lrow, lhalf * 8 + q)) = hv;
            }
        }
        __syncthreads();

        for (int t = t0; t <= t1; ++t) {
            const uint32_t bw = sbase + WB + (uint32_t)t * 32768u;

            float acc[2][8][4];
            #pragma unroll
            for (int i = 0; i < 2; i++)
                #pragma unroll
                for (int j = 0; j < 8; j++)
                    #pragma unroll
                    for (int p = 0; p < 4; p++) acc[i][j][p] = 0.f;

            #pragma unroll
            for (int ks = 0; ks < 8; ks++) {
                // ---- A fragments ------------------------------------------
                uint32_t ah[2][4];
                {
                    const int r    = lane & 7;
                    const int half = (lane >> 3) & 1;
                    const int ksel = lane >> 4;
                    const int akc  = ks * 2 + ksel;
                    #pragma unroll
                    for (int mt = 0; mt < 2; mt++) {
                        const uint32_t aoff = SW_OFF(m0 + mt * 16 + half * 8 + r, akc);
                        ldsm_x4(ah[mt][0], ah[mt][1], ah[mt][2], ah[mt][3],
                                sbase + XH + aoff);
                    }
                }
                // ---- B fragments (64 cols) --------------------------------
                uint32_t bh[8][2];
                {
                    const int r    = lane & 7;
                    const int ksel = (lane >> 3) & 1;
                    const int jsel = lane >> 4;
                    const int bkc  = ks * 2 + ksel;
                    #pragma unroll
                    for (int jj = 0; jj < 4; jj++) {
                        const uint32_t boff = SW_OFF(n0 + jj * 16 + jsel * 8 + r, bkc);
                        uint32_t r0, r1, r2, r3;
                        ldsm_x4(r0, r1, r2, r3, bw + boff);
                        bh[2 * jj][0] = r0;     bh[2 * jj][1] = r1;
                        bh[2 * jj + 1][0] = r2; bh[2 * jj + 1][1] = r3;
                    }
                }
                // ---- 16 MMAs ----------------------------------------------
                #pragma unroll
                for (int mt = 0; mt < 2; mt++)
                    #pragma unroll
                    for (int nt = 0; nt < 8; nt++)
                        mma_f16(acc[mt][nt], ah[mt], bh[nt]);
            }

            // ---- epilogue: masked writeout (fp16 for v, fp32 for out) ------
            {
                const int g  = lane >> 2;
                const int c2 = (lane & 3) * 2;
                #pragma unroll
                for (int mt = 0; mt < 2; mt++) {
                    #pragma unroll
                    for (int half = 0; half < 2; half++) {
                        const int growo = row0 + m0 + mt * 16 + half * 8 + g;
                        if (growo < N && (!mixed || ntype[growo] == t)) {
                            if (out_half) {
                                __half* yp = Yh + (size_t)growo * DIM + n0 + c2;
                                #pragma unroll
                                for (int nt = 0; nt < 8; nt++)
                                    *(__half2*)(yp + nt * 8) =
                                        __floats2half2_rn(acc[mt][nt][half * 2],
                                                          acc[mt][nt][half * 2 + 1]);
                            } else {
                                float2* yp = (float2*)(Yf + (size_t)growo * DIM + n0 + c2);
                                #pragma unroll
                                for (int nt = 0; nt < 8; nt++)
                                    yp[nt * 4] = make_float2(acc[mt][nt][half * 2],
                                                             acc[mt][nt][half * 2 + 1]);
                            }
                        }
                    }
                }
            }
        }
    }
}

// ---------------------------------------------------------------------------
// Edge scatter-sum: g_h[dst[e],:] += v[src[e],:], all fp16. 8 edges per warp:
// uniform int4 index loads, 8 independent fp16 gathers (8B/lane = 4 halves),
// 8 fire-and-forget red.global.add.noftz.v2.f16x2 (no conversion at all).
// LTS bytes: 205MB gather + 205MB RED (was 615MB with fp32 h).
// ---------------------------------------------------------------------------
__global__ __launch_bounds__(256) void scatter_kernel(
    const int* __restrict__ src, const int* __restrict__ dst)
{
    const int w    = (int)((blockIdx.x * (unsigned)blockDim.x + threadIdx.x) >> 5);
    const int lane = threadIdx.x & 31;
    const int4 s0 = __ldg((const int4*)src + w * 2);
    const int4 s1 = __ldg((const int4*)src + w * 2 + 1);
    const int4 d0 = __ldg((const int4*)dst + w * 2);
    const int4 d1 = __ldg((const int4*)dst + w * 2 + 1);
    const int s[8] = {s0.x, s0.y, s0.z, s0.w, s1.x, s1.y, s1.z, s1.w};
    const int d[8] = {d0.x, d0.y, d0.z, d0.w, d1.x, d1.y, d1.z, d1.w};

    uint2 raw[8];
    #pragma unroll
    for (int i = 0; i < 8; i++)
        raw[i] = ((const uint2*)(g_v + (size_t)s[i] * DIM))[lane];

    #pragma unroll
    for (int i = 0; i < 8; i++) {
        __half* hd = g_h + (size_t)d[i] * DIM + lane * 4;   // 4 halves = 8B
        asm volatile("red.global.add.noftz.v2.f16x2 [%0], {%1, %2};"
                     :: "l"(hd), "r"(raw[i].x), "r"(raw[i].y)
                     : "memory");
    }
}

// ---------------------------------------------------------------------------
extern "C" void kernel_launch(void* const* d_in, const int* in_sizes, int n_in,
                              void* d_out, int out_size)
{
    const float* x     = (const float*)d_in[0];
    const int*   ntype = (const int*)  d_in[1];
    const int*   src   = (const int*)  d_in[2];
    const int*   dst   = (const int*)  d_in[3];
    const float* W_v   = (const float*)d_in[4];
    const float* W_a   = (const float*)d_in[5];
    float*       out   = (float*)d_out;

    __half* v_ptr;
    __half* h_ptr;
    cudaGetSymbolAddress((void**)&v_ptr, g_v);
    cudaGetSymbolAddress((void**)&h_ptr, g_h);

    const int N = N_NODES;
    const int SMEM_DYN = 98304;   // Xh (32K) + W both types (64K)
    cudaFuncSetAttribute(gemm_mma_kernel,
                         cudaFuncAttributeMaxDynamicSharedMemorySize, SMEM_DYN);

    // prepack W (fp16 swizzled SMEM images)
    prepack_kernel<<<(4 * 128 * 128 + 255) / 256, 256>>>(W_v, W_a);
    // v = typed_linear(x, W_v, ntype) -> fp16; + fire-and-forget zero of g_h
    gemm_mma_kernel<<<296, 256, SMEM_DYN>>>(x, nullptr, 0, 1, 0, 1,
                                            ntype, nullptr, v_ptr, N);
    // h[dst] += v[src]  (8 edges/warp, pure fp16 RED)
    scatter_kernel<<<N_EDGES / 8 / 8, 256>>>(src, dst);
    // out = typed_linear(h, W_a, ntype) -> fp32  (h read as fp16, no cvt)
    gemm_mma_kernel<<<296, 256, SMEM_DYN>>>(nullptr, h_ptr, 1, 0, 1, 0,
                                            ntype, out, nullptr, N);
}